// round 13
// baseline (speedup 1.0000x reference)
#include <cuda_runtime.h>
#include <cuda_fp16.h>

#define D 4096
#define NSTEPS 50
#define NCTA 147
#define ROWS_PER_CTA 28
#define CACHED_ROWS 12           // rows per CTA held in SMEM (192 KB)
#define NTHREADS 896             // 28 warps: rg 0..6 x ks 0..3, zero idle

// Interleaved fp16 pairs: g_AB[r*2D + 2j] = M[r][j] = A+B, [..+1] = -B[r][j].
// Recurrence: theta_{t+1} = M theta_t + (-B) theta_{t-1}.
__device__ __align__(16) __half g_AB[(size_t)2 * D * D];
__device__ unsigned int g_bar;      // arrival counter (monotonic per launch)
__device__ unsigned int g_release;  // step release word (single writer per step)

// ---------------------------------------------------------------------------
// prep: build interleaved (A+B, -B) fp16 pairs; reset barrier words.
// ---------------------------------------------------------------------------
__global__ void __launch_bounds__(256) prep_kernel(const float* __restrict__ A,
                                                   const float* __restrict__ B) {
    if (blockIdx.x == 0 && threadIdx.x == 0) { g_bar = 0; g_release = 0; }
    size_t i = (size_t)blockIdx.x * blockDim.x + threadIdx.x;  // float4 index
    float4 a = ((const float4*)A)[i];
    float4 b = ((const float4*)B)[i];
    uint4 o;
    __half2 p;
    p = __floats2half2_rn(a.x + b.x, -b.x); o.x = *(unsigned int*)&p;
    p = __floats2half2_rn(a.y + b.y, -b.y); o.y = *(unsigned int*)&p;
    p = __floats2half2_rn(a.z + b.z, -b.z); o.z = *(unsigned int*)&p;
    p = __floats2half2_rn(a.w + b.w, -b.w); o.w = *(unsigned int*)&p;
    ((uint4*)g_AB)[i] = o;
}

// acc += M[j]*cur + (-B)[j]*prev for 4 interleaved fp16 pairs in m
__device__ __forceinline__ float dotAB(uint4 m, float4 c, float4 p, float acc) {
    float2 f;
    f = __half22float2(*(__half2*)&m.x); acc = fmaf(f.x, c.x, acc); acc = fmaf(f.y, p.x, acc);
    f = __half22float2(*(__half2*)&m.y); acc = fmaf(f.x, c.y, acc); acc = fmaf(f.y, p.y, acc);
    f = __half22float2(*(__half2*)&m.z); acc = fmaf(f.x, c.z, acc); acc = fmaf(f.y, p.z, acc);
    f = __half22float2(*(__half2*)&m.w); acc = fmaf(f.x, c.w, acc); acc = fmaf(f.y, p.w, acc);
    return acc;
}

// ---------------------------------------------------------------------------
// Persistent recurrence kernel: 147 CTAs x 896 threads (28 warps, none idle).
// Warp (rg, ks): 4-row group x 1024-elem K-segment.  No block-wide vector
// staging: each warp loads its cur-segment straight from global into
// registers (overlapped with matrix loads); prev comes from a parity-double-
// buffered SMEM copy that the rg==0 warp of each segment deposits from its
// cur registers (ordered for next-step readers by the end-of-step syncs).
// Rows 0..11 cached in SMEM; rows 12..27 stream from L2.
// Barrier: atomicAdd arrivals + single-writer release word (proven).
// SMEM: v0 16K | v1 16K | part 512B | cached rows 192K = 224.5 KB.
// ---------------------------------------------------------------------------
__global__ void __launch_bounds__(NTHREADS, 1) rnn_kernel(const float* __restrict__ init,
                                                          float* __restrict__ out) {
    extern __shared__ char smem[];
    float4* s_v0   = (float4*)smem;                    // vector buffer 0 (16 KB)
    float4* s_v1   = (float4*)(smem + 16384);          // vector buffer 1 (16 KB)
    float*  s_part = (float*)(smem + 32768);           // partials (512 B)
    uint4*  s_mat  = (uint4*)(smem + 33280);           // cached rows (192 KB)

    const int tid  = threadIdx.x;
    const int warp = tid >> 5;                         // 0..27
    const int lane = tid & 31;
    const int rg   = warp >> 2;                        // 0..6
    const int ks   = warp & 3;                         // 0..3
    const int row_base = blockIdx.x * ROWS_PER_CTA;
    const int row0 = row_base + rg * 4;
    const bool rowOK  = (row0 < D);                    // CTA 146 rg>=2 invalid
    const bool cached = (rg < CACHED_ROWS / 4);        // rg 0..2 -> SMEM rows
    const int seg = ks * 256;                          // float4 offset of segment

    // Preload cached rows into SMEM (once).  Clamp OOB rows of the last CTA.
#pragma unroll
    for (int it = 0; it < CACHED_ROWS; ++it) {
        int sr = min(row_base + it, D - 1);
        for (int i = tid; i < 1024; i += NTHREADS)
            s_mat[it * 1024 + i] = ((const uint4*)g_AB)[(size_t)sr * 1024 + i];
    }

    // Streamed-row pointers (rg >= 3), clamped for the partially-OOB last CTA
    const uint4* r0 = (const uint4*)g_AB + (size_t)min(row0 + 0, D - 1) * 1024;
    const uint4* r1 = (const uint4*)g_AB + (size_t)min(row0 + 1, D - 1) * 1024;
    const uint4* r2 = (const uint4*)g_AB + (size_t)min(row0 + 2, D - 1) * 1024;
    const uint4* r3 = (const uint4*)g_AB + (size_t)min(row0 + 3, D - 1) * 1024;
    // Cached-row pointers (rg < 3)
    const uint4* c0 = s_mat + (size_t)(rg * 4 + 0) * 1024;
    const uint4* c1 = s_mat + (size_t)(rg * 4 + 1) * 1024;
    const uint4* c2 = s_mat + (size_t)(rg * 4 + 2) * 1024;
    const uint4* c3 = s_mat + (size_t)(rg * 4 + 3) * 1024;

    // Prologue: buf1 holds theta_{-1} = init_seq[0]  (prev for t=0 is buf[(t-1)&1]=buf1)
    for (int i = tid; i < 1024; i += NTHREADS)
        s_v1[i] = ((const float4*)init)[i];
    __syncthreads();

    for (int t = 0; t < NSTEPS; ++t) {
        float4* wbuf = (t & 1) ? s_v1 : s_v0;          // cur deposited here (rg0)
        const float4* pbuf = (t & 1) ? s_v0 : s_v1;    // prev (theta_{t-1})

        // Per-warp direct load of this warp's cur segment (8 float4 / lane),
        // overlapping the matrix loads below.  No block staging, no sync.
        const float* th1 = (t == 0) ? init + D : out + (size_t)(t - 1) * D;
        const float4* cg = (const float4*)th1 + seg;
        float4 cv[8];
#pragma unroll
        for (int i = 0; i < 8; ++i)
            cv[i] = __ldcg(cg + i * 32 + lane);

        float a0 = 0.f, a1 = 0.f, a2 = 0.f, a3 = 0.f;
        if (cached) {
#pragma unroll 2
            for (int i = 0; i < 8; ++i) {
                int idx = seg + i * 32 + lane;
                float4 pv = pbuf[idx];
                a0 = dotAB(c0[idx], cv[i], pv, a0);
                a1 = dotAB(c1[idx], cv[i], pv, a1);
                a2 = dotAB(c2[idx], cv[i], pv, a2);
                a3 = dotAB(c3[idx], cv[i], pv, a3);
            }
        } else if (rowOK) {
#pragma unroll 2
            for (int i = 0; i < 8; ++i) {
                int idx = seg + i * 32 + lane;
                uint4 m0 = r0[idx];
                uint4 m1 = r1[idx];
                uint4 m2 = r2[idx];
                uint4 m3 = r3[idx];
                float4 pv = pbuf[idx];
                a0 = dotAB(m0, cv[i], pv, a0);
                a1 = dotAB(m1, cv[i], pv, a1);
                a2 = dotAB(m2, cv[i], pv, a2);
                a3 = dotAB(m3, cv[i], pv, a3);
            }
        }

        // rg0 warp of each segment deposits cur into the next-prev buffer.
        // Readers touch it only after the end-of-step __syncthreads.
        if (rg == 0) {
#pragma unroll
            for (int i = 0; i < 8; ++i)
                wbuf[seg + i * 32 + lane] = cv[i];
        }

        if (rowOK) {
#pragma unroll
            for (int off = 16; off; off >>= 1) {
                a0 += __shfl_xor_sync(0xffffffffu, a0, off);
                a1 += __shfl_xor_sync(0xffffffffu, a1, off);
                a2 += __shfl_xor_sync(0xffffffffu, a2, off);
                a3 += __shfl_xor_sync(0xffffffffu, a3, off);
            }
            if (lane == 0) {
                s_part[(rg * 4 + 0) * 4 + ks] = a0;
                s_part[(rg * 4 + 1) * 4 + ks] = a1;
                s_part[(rg * 4 + 2) * 4 + ks] = a2;
                s_part[(rg * 4 + 3) * 4 + ks] = a3;
            }
        }
        __syncthreads();                               // partials + wbuf ready

        // Warp 0: combine partials, publish rows, run the step barrier
        if (warp == 0) {
            if (tid < ROWS_PER_CTA) {
                int row = row_base + tid;
                if (row < D) {
                    float v = (s_part[tid * 4 + 0] + s_part[tid * 4 + 1]) +
                              (s_part[tid * 4 + 2] + s_part[tid * 4 + 3]);
                    __stcg(out + (size_t)t * D + row, v);
                }
            }
            __syncwarp();
            if (lane == 0) {
                __threadfence();                       // release this CTA's rows
                unsigned int old = atomicAdd(&g_bar, 1u);
                unsigned int target = (unsigned int)(t + 1) * NCTA;
                if (old == target - 1u)
                    *(volatile unsigned int*)&g_release = (unsigned int)(t + 1);
                while (*(volatile unsigned int*)&g_release < (unsigned int)(t + 1)) { }
                __threadfence();                       // acquire
            }
            __syncwarp();
        }
        __syncthreads();                               // release all warps
    }
}

// ---------------------------------------------------------------------------
// Launch: prep (convert + barrier reset), then ONE persistent kernel with
// opt-in 224.5 KB dynamic SMEM (1 CTA/SM, 147 co-resident).
// ---------------------------------------------------------------------------
extern "C" void kernel_launch(void* const* d_in, const int* in_sizes, int n_in,
                              void* d_out, int out_size) {
    const float* init = (const float*)d_in[0];  // [2, D]
    const float* A    = (const float*)d_in[1];  // [D, D]
    const float* B    = (const float*)d_in[2];  // [D, D]
    float* out = (float*)d_out;                 // [NSTEPS, D]

    const int smem_bytes = 33280 + CACHED_ROWS * 1024 * 16;  // 229,888 B
    cudaFuncSetAttribute(rnn_kernel, cudaFuncAttributeMaxDynamicSharedMemorySize,
                         smem_bytes);

    prep_kernel<<<(D * (size_t)D / 4) / 256, 256>>>(A, B);
    rnn_kernel<<<NCTA, NTHREADS, smem_bytes>>>(init, out);
}

// round 14
// speedup vs baseline: 1.7825x; 1.7825x over previous
#include <cuda_runtime.h>
#include <cuda_fp16.h>

#define D 4096
#define NSTEPS 50
#define NCTA 147
#define ROWS_PER_CTA 28
#define CACHED_ROWS 12           // rows per CTA held in SMEM (192 KB)
#define NTHREADS 1024
#define NBAR 8                   // barrier counter shards (distinct L2 lines)

// Interleaved fp16 matrices: g_AB[r*2D + 2j] = A[r][j], [.. + 1] = B[r][j].
__device__ __align__(16) __half g_AB[(size_t)2 * D * D];
// Sharded arrival counters, 128B stride -> 8 distinct L2 lines.
// CTA i arrives at shard i&7 (<=19 serialized atomics instead of 147).
__device__ unsigned int g_bar[NBAR * 32];

// ---------------------------------------------------------------------------
// prep: interleave A,B into fp16 pairs; reset the barrier shards.
// ---------------------------------------------------------------------------
__global__ void __launch_bounds__(256) prep_kernel(const float* __restrict__ A,
                                                   const float* __restrict__ B) {
    if (blockIdx.x == 0 && threadIdx.x < NBAR * 32) g_bar[threadIdx.x] = 0;
    size_t i = (size_t)blockIdx.x * blockDim.x + threadIdx.x;  // float4 index
    float4 a = ((const float4*)A)[i];
    float4 b = ((const float4*)B)[i];
    uint4 o;
    __half2 p;
    p = __floats2half2_rn(a.x, b.x); o.x = *(unsigned int*)&p;
    p = __floats2half2_rn(a.y, b.y); o.y = *(unsigned int*)&p;
    p = __floats2half2_rn(a.z, b.z); o.z = *(unsigned int*)&p;
    p = __floats2half2_rn(a.w, b.w); o.w = *(unsigned int*)&p;
    ((uint4*)g_AB)[i] = o;
}

// acc += A[j]*t + B[j]*d for 4 interleaved (a,b) fp16 pairs in m
__device__ __forceinline__ float dotAB(uint4 m, float4 t, float4 d, float acc) {
    float2 f;
    f = __half22float2(*(__half2*)&m.x); acc = fmaf(f.x, t.x, acc); acc = fmaf(f.y, d.x, acc);
    f = __half22float2(*(__half2*)&m.y); acc = fmaf(f.x, t.y, acc); acc = fmaf(f.y, d.y, acc);
    f = __half22float2(*(__half2*)&m.z); acc = fmaf(f.x, t.z, acc); acc = fmaf(f.y, d.z, acc);
    f = __half22float2(*(__half2*)&m.w); acc = fmaf(f.x, t.w, acc); acc = fmaf(f.y, d.w, acc);
    return acc;
}

// ---------------------------------------------------------------------------
// Persistent recurrence kernel: 147 CTAs x 1024 threads, 28 rows/CTA.
// IDENTICAL to the best (338.8us) kernel except the device-wide barrier:
// arrivals are sharded over 8 counters (atomicAdd to shard bid&7), and every
// CTA's tid0 polls the SUM of the 8 monotonic counters.  Same semantics as
// the proven single-counter spin (monotonic, never reset mid-run, all CTAs
// co-resident at 1 CTA/SM) but ~8x less same-address atomic serialization.
// ---------------------------------------------------------------------------
__global__ void __launch_bounds__(NTHREADS, 1) rnn_kernel(const float* __restrict__ init,
                                                          float* __restrict__ out) {
    extern __shared__ char smem[];
    float4* s_t    = (float4*)smem;                    // theta_t   (16 KB)
    float4* s_d    = (float4*)(smem + 16384);          // delta     (16 KB)
    float*  s_part = (float*)(smem + 32768);           // partials  (512 B)
    uint4*  s_mat  = (uint4*)(smem + 33280);           // cached rows (192 KB)

    const int tid  = threadIdx.x;
    const int warp = tid >> 5;
    const int lane = tid & 31;
    const int rg   = warp >> 2;                        // 0..7 (7 idle)
    const int ks   = warp & 3;                         // 0..3
    const int row_base = blockIdx.x * ROWS_PER_CTA;
    const int row0 = row_base + rg * 4;
    const bool rowOK  = (rg < 7) && (row0 < D);
    const bool cached = (rg < CACHED_ROWS / 4);        // rg 0..2 -> SMEM rows
    const int seg = ks * 256;                          // float4 offset of segment

    // Preload cached rows into SMEM (once).  Clamp OOB rows of the last CTA.
#pragma unroll
    for (int it = 0; it < CACHED_ROWS; ++it) {
        int sr = min(row_base + it, D - 1);
        s_mat[it * 1024 + tid] = ((const uint4*)g_AB)[(size_t)sr * 1024 + tid];
    }

    // Streamed-row pointers (rg >= 3), clamped for the partially-OOB last CTA
    const uint4* r0 = (const uint4*)g_AB + (size_t)min(row0 + 0, D - 1) * 1024;
    const uint4* r1 = (const uint4*)g_AB + (size_t)min(row0 + 1, D - 1) * 1024;
    const uint4* r2 = (const uint4*)g_AB + (size_t)min(row0 + 2, D - 1) * 1024;
    const uint4* r3 = (const uint4*)g_AB + (size_t)min(row0 + 3, D - 1) * 1024;
    // Cached-row pointers (rg < 3)
    const uint4* c0 = s_mat + (size_t)(rg * 4 + 0) * 1024;
    const uint4* c1 = s_mat + (size_t)(rg * 4 + 1) * 1024;
    const uint4* c2 = s_mat + (size_t)(rg * 4 + 2) * 1024;
    const uint4* c3 = s_mat + (size_t)(rg * 4 + 3) * 1024;

    // Prologue: s_t holds theta_{-1} = init_seq[0]
    s_t[tid] = ((const float4*)init)[tid];

    for (int t = 0; t < NSTEPS; ++t) {
        // Stage theta_t; delta = theta_t - theta_{t-1} (prev step's s_t)
        const float* th1 = (t == 0) ? init + D : out + (size_t)(t - 1) * D;
        float4 nt = __ldcg((const float4*)th1 + tid);
        float4 pt = s_t[tid];
        s_t[tid] = nt;
        s_d[tid] = make_float4(nt.x - pt.x, nt.y - pt.y, nt.z - pt.z, nt.w - pt.w);
        __syncthreads();

        if (rowOK) {
            float a0 = 0.f, a1 = 0.f, a2 = 0.f, a3 = 0.f;
            if (cached) {
#pragma unroll 2
                for (int i = 0; i < 8; ++i) {
                    int idx = seg + i * 32 + lane;
                    float4 t4 = s_t[idx];
                    float4 d4 = s_d[idx];
                    a0 = dotAB(c0[idx], t4, d4, a0);
                    a1 = dotAB(c1[idx], t4, d4, a1);
                    a2 = dotAB(c2[idx], t4, d4, a2);
                    a3 = dotAB(c3[idx], t4, d4, a3);
                }
            } else {
#pragma unroll 2
                for (int i = 0; i < 8; ++i) {
                    int idx = seg + i * 32 + lane;
                    uint4 m0 = r0[idx];
                    uint4 m1 = r1[idx];
                    uint4 m2 = r2[idx];
                    uint4 m3 = r3[idx];
                    float4 t4 = s_t[idx];
                    float4 d4 = s_d[idx];
                    a0 = dotAB(m0, t4, d4, a0);
                    a1 = dotAB(m1, t4, d4, a1);
                    a2 = dotAB(m2, t4, d4, a2);
                    a3 = dotAB(m3, t4, d4, a3);
                }
            }
#pragma unroll
            for (int off = 16; off; off >>= 1) {
                a0 += __shfl_xor_sync(0xffffffffu, a0, off);
                a1 += __shfl_xor_sync(0xffffffffu, a1, off);
                a2 += __shfl_xor_sync(0xffffffffu, a2, off);
                a3 += __shfl_xor_sync(0xffffffffu, a3, off);
            }
            if (lane == 0) {
                s_part[(rg * 4 + 0) * 4 + ks] = a0;
                s_part[(rg * 4 + 1) * 4 + ks] = a1;
                s_part[(rg * 4 + 2) * 4 + ks] = a2;
                s_part[(rg * 4 + 3) * 4 + ks] = a3;
            }
        }
        __syncthreads();

        // Combine K-segment partials (deterministic order) and publish rows
        if (tid < ROWS_PER_CTA) {
            int row = row_base + tid;
            if (row < D) {
                float v = (s_part[tid * 4 + 0] + s_part[tid * 4 + 1]) +
                          (s_part[tid * 4 + 2] + s_part[tid * 4 + 3]);
                __stcg(out + (size_t)t * D + row, v);
            }
        }
        __syncthreads();

        // Device-wide step barrier, sharded over NBAR counters.
        if (tid == 0) {
            __threadfence();                           // release this CTA's rows
            atomicAdd(&g_bar[(blockIdx.x & (NBAR - 1)) * 32], 1u);
            const unsigned int target = (unsigned int)(t + 1) * NCTA;
            unsigned int sum;
            do {
                sum = 0;
#pragma unroll
                for (int k = 0; k < NBAR; ++k)
                    sum += *(volatile unsigned int*)&g_bar[k * 32];
            } while (sum < target);
            __threadfence();                           // acquire
        }
        __syncthreads();
    }
}

// ---------------------------------------------------------------------------
// Launch: prep (convert + barrier reset), then ONE persistent kernel with
// opt-in 224.5 KB dynamic SMEM (1 CTA/SM, 147 co-resident).
// ---------------------------------------------------------------------------
extern "C" void kernel_launch(void* const* d_in, const int* in_sizes, int n_in,
                              void* d_out, int out_size) {
    const float* init = (const float*)d_in[0];  // [2, D]
    const float* A    = (const float*)d_in[1];  // [D, D]
    const float* B    = (const float*)d_in[2];  // [D, D]
    float* out = (float*)d_out;                 // [NSTEPS, D]

    const int smem_bytes = 33280 + CACHED_ROWS * 1024 * 16;  // 229,888 B
    cudaFuncSetAttribute(rnn_kernel, cudaFuncAttributeMaxDynamicSharedMemorySize,
                         smem_bytes);

    prep_kernel<<<(D * (size_t)D / 4) / 256, 256>>>(A, B);
    rnn_kernel<<<NCTA, NTHREADS, smem_bytes>>>(init, out);
}

// round 15
// speedup vs baseline: 1.9364x; 1.0863x over previous
#include <cuda_runtime.h>
#include <cuda_fp16.h>

#define D 4096
#define NSTEPS 50
#define NCTA 147
#define ROWS_PER_CTA 28
#define CACHED_ROWS 12           // rows per CTA held in SMEM (192 KB)
#define NTHREADS 1024
#define NBAR 8                   // barrier counter shards (distinct L2 lines)

// Interleaved fp16 matrices: g_AB[r*2D + 2j] = A[r][j] (lo), [..+1] = B[r][j] (hi).
__device__ __align__(16) __half g_AB[(size_t)2 * D * D];
// Sharded arrival counters, 128B stride -> 8 distinct L2 lines.
__device__ unsigned int g_bar[NBAR * 32];

// ---------------------------------------------------------------------------
// prep: interleave A,B into fp16 pairs; reset the barrier shards.
// ---------------------------------------------------------------------------
__global__ void __launch_bounds__(256) prep_kernel(const float* __restrict__ A,
                                                   const float* __restrict__ B) {
    if (blockIdx.x == 0 && threadIdx.x < NBAR * 32) g_bar[threadIdx.x] = 0;
    size_t i = (size_t)blockIdx.x * blockDim.x + threadIdx.x;  // float4 index
    float4 a = ((const float4*)A)[i];
    float4 b = ((const float4*)B)[i];
    uint4 o;
    __half2 p;
    p = __floats2half2_rn(a.x, b.x); o.x = *(unsigned int*)&p;   // lo=A, hi=B
    p = __floats2half2_rn(a.y, b.y); o.y = *(unsigned int*)&p;
    p = __floats2half2_rn(a.z, b.z); o.z = *(unsigned int*)&p;
    p = __floats2half2_rn(a.w, b.w); o.w = *(unsigned int*)&p;
    ((uint4*)g_AB)[i] = o;
}

// acc += Sum_j(A_j*t_j) + Sum_j(B_j*d_j) over 4 elements:
// m = 4x half2 (a,b);  v = 4x half2 (t,d).  HFMA2 accumulates (a*t, b*d)
// pairwise in fp16 (only 4 products per half-lane -> negligible error),
// then one fold into the fp32 accumulator.  No cvts on the matrix data.
__device__ __forceinline__ float dotAB(uint4 m, uint4 v, float acc) {
    __half2 p = __hmul2(*(__half2*)&m.x, *(__half2*)&v.x);
    p = __hfma2(*(__half2*)&m.y, *(__half2*)&v.y, p);
    p = __hfma2(*(__half2*)&m.z, *(__half2*)&v.z, p);
    p = __hfma2(*(__half2*)&m.w, *(__half2*)&v.w, p);
    float2 f = __half22float2(p);
    return acc + f.x + f.y;
}

// ---------------------------------------------------------------------------
// Persistent recurrence kernel: 147 CTAs x 1024 threads, 28 rows/CTA.
// Same structure as the 334.6us kernel; the staged vector is now interleaved
// (theta, delta) half2 pairs (s_td), so the inner loop is pure HFMA2 with an
// fp32 fold — no converts, half the vector LDS bytes.  s_t keeps the fp32
// theta for next step's delta.  Sharded-counter barrier (proven R14).
// SMEM: s_t 16K | s_td 16K | part 512B | cached rows 192K = 224.5 KB.
// ---------------------------------------------------------------------------
__global__ void __launch_bounds__(NTHREADS, 1) rnn_kernel(const float* __restrict__ init,
                                                          float* __restrict__ out) {
    extern __shared__ char smem[];
    float4* s_t    = (float4*)smem;                    // theta_t fp32   (16 KB)
    uint4*  s_td   = (uint4*)(smem + 16384);           // (t,d) half2    (16 KB)
    float*  s_part = (float*)(smem + 32768);           // partials       (512 B)
    uint4*  s_mat  = (uint4*)(smem + 33280);           // cached rows    (192 KB)

    const int tid  = threadIdx.x;
    const int warp = tid >> 5;
    const int lane = tid & 31;
    const int rg   = warp >> 2;                        // 0..7 (7 idle)
    const int ks   = warp & 3;                         // 0..3
    const int row_base = blockIdx.x * ROWS_PER_CTA;
    const int row0 = row_base + rg * 4;
    const bool rowOK  = (rg < 7) && (row0 < D);
    const bool cached = (rg < CACHED_ROWS / 4);        // rg 0..2 -> SMEM rows
    const int seg = ks * 256;                          // uint4 offset of segment

    // Preload cached rows into SMEM (once).  Clamp OOB rows of the last CTA.
#pragma unroll
    for (int it = 0; it < CACHED_ROWS; ++it) {
        int sr = min(row_base + it, D - 1);
        s_mat[it * 1024 + tid] = ((const uint4*)g_AB)[(size_t)sr * 1024 + tid];
    }

    // Streamed-row pointers (rg >= 3), clamped for the partially-OOB last CTA
    const uint4* r0 = (const uint4*)g_AB + (size_t)min(row0 + 0, D - 1) * 1024;
    const uint4* r1 = (const uint4*)g_AB + (size_t)min(row0 + 1, D - 1) * 1024;
    const uint4* r2 = (const uint4*)g_AB + (size_t)min(row0 + 2, D - 1) * 1024;
    const uint4* r3 = (const uint4*)g_AB + (size_t)min(row0 + 3, D - 1) * 1024;
    // Cached-row pointers (rg < 3)
    const uint4* c0 = s_mat + (size_t)(rg * 4 + 0) * 1024;
    const uint4* c1 = s_mat + (size_t)(rg * 4 + 1) * 1024;
    const uint4* c2 = s_mat + (size_t)(rg * 4 + 2) * 1024;
    const uint4* c3 = s_mat + (size_t)(rg * 4 + 3) * 1024;

    // Prologue: s_t holds theta_{-1} = init_seq[0]
    s_t[tid] = ((const float4*)init)[tid];

    for (int t = 0; t < NSTEPS; ++t) {
        // Stage theta_t: pack (theta, delta) half2 pairs; keep fp32 theta.
        const float* th1 = (t == 0) ? init + D : out + (size_t)(t - 1) * D;
        float4 nt = __ldcg((const float4*)th1 + tid);
        float4 pt = s_t[tid];
        s_t[tid] = nt;
        {
            uint4 v;
            __half2 h;
            h = __floats2half2_rn(nt.x, nt.x - pt.x); v.x = *(unsigned int*)&h;
            h = __floats2half2_rn(nt.y, nt.y - pt.y); v.y = *(unsigned int*)&h;
            h = __floats2half2_rn(nt.z, nt.z - pt.z); v.z = *(unsigned int*)&h;
            h = __floats2half2_rn(nt.w, nt.w - pt.w); v.w = *(unsigned int*)&h;
            s_td[tid] = v;
        }
        __syncthreads();

        if (rowOK) {
            float a0 = 0.f, a1 = 0.f, a2 = 0.f, a3 = 0.f;
            if (cached) {
#pragma unroll 2
                for (int i = 0; i < 8; ++i) {
                    int idx = seg + i * 32 + lane;
                    uint4 v = s_td[idx];
                    a0 = dotAB(c0[idx], v, a0);
                    a1 = dotAB(c1[idx], v, a1);
                    a2 = dotAB(c2[idx], v, a2);
                    a3 = dotAB(c3[idx], v, a3);
                }
            } else {
#pragma unroll 2
                for (int i = 0; i < 8; ++i) {
                    int idx = seg + i * 32 + lane;
                    uint4 m0 = r0[idx];
                    uint4 m1 = r1[idx];
                    uint4 m2 = r2[idx];
                    uint4 m3 = r3[idx];
                    uint4 v = s_td[idx];
                    a0 = dotAB(m0, v, a0);
                    a1 = dotAB(m1, v, a1);
                    a2 = dotAB(m2, v, a2);
                    a3 = dotAB(m3, v, a3);
                }
            }
#pragma unroll
            for (int off = 16; off; off >>= 1) {
                a0 += __shfl_xor_sync(0xffffffffu, a0, off);
                a1 += __shfl_xor_sync(0xffffffffu, a1, off);
                a2 += __shfl_xor_sync(0xffffffffu, a2, off);
                a3 += __shfl_xor_sync(0xffffffffu, a3, off);
            }
            if (lane == 0) {
                s_part[(rg * 4 + 0) * 4 + ks] = a0;
                s_part[(rg * 4 + 1) * 4 + ks] = a1;
                s_part[(rg * 4 + 2) * 4 + ks] = a2;
                s_part[(rg * 4 + 3) * 4 + ks] = a3;
            }
        }
        __syncthreads();

        // Combine K-segment partials (deterministic order) and publish rows
        if (tid < ROWS_PER_CTA) {
            int row = row_base + tid;
            if (row < D) {
                float v = (s_part[tid * 4 + 0] + s_part[tid * 4 + 1]) +
                          (s_part[tid * 4 + 2] + s_part[tid * 4 + 3]);
                __stcg(out + (size_t)t * D + row, v);
            }
        }
        __syncthreads();

        // Device-wide step barrier, sharded over NBAR counters (proven R14).
        if (tid == 0) {
            __threadfence();                           // release this CTA's rows
            atomicAdd(&g_bar[(blockIdx.x & (NBAR - 1)) * 32], 1u);
            const unsigned int target = (unsigned int)(t + 1) * NCTA;
            unsigned int sum;
            do {
                sum = 0;
#pragma unroll
                for (int k = 0; k < NBAR; ++k)
                    sum += *(volatile unsigned int*)&g_bar[k * 32];
            } while (sum < target);
            __threadfence();                           // acquire
        }
        __syncthreads();
    }
}

// ---------------------------------------------------------------------------
// Launch: prep (convert + barrier reset), then ONE persistent kernel with
// opt-in 224.5 KB dynamic SMEM (1 CTA/SM, 147 co-resident).
// ---------------------------------------------------------------------------
extern "C" void kernel_launch(void* const* d_in, const int* in_sizes, int n_in,
                              void* d_out, int out_size) {
    const float* init = (const float*)d_in[0];  // [2, D]
    const float* A    = (const float*)d_in[1];  // [D, D]
    const float* B    = (const float*)d_in[2];  // [D, D]
    float* out = (float*)d_out;                 // [NSTEPS, D]

    const int smem_bytes = 33280 + CACHED_ROWS * 1024 * 16;  // 229,888 B
    cudaFuncSetAttribute(rnn_kernel, cudaFuncAttributeMaxDynamicSharedMemorySize,
                         smem_bytes);

    prep_kernel<<<(D * (size_t)D / 4) / 256, 256>>>(A, B);
    rnn_kernel<<<NCTA, NTHREADS, smem_bytes>>>(init, out);
}

// round 16
// speedup vs baseline: 1.9406x; 1.0022x over previous
#include <cuda_runtime.h>
#include <cuda_fp16.h>

#define D 4096
#define NSTEPS 50
#define NCTA 147
#define ROWS_PER_CTA 28
#define CACHED_ROWS 12           // rows per CTA held in SMEM (192 KB)
#define NTHREADS 1024
#define NBAR 8                   // barrier counter shards (distinct L2 lines)

// Interleaved fp16 matrices: g_AB[r*2D + 2j] = A[r][j] (lo), [..+1] = B[r][j] (hi).
__device__ __align__(16) __half g_AB[(size_t)2 * D * D];
// Packed (theta_t, delta_t) half2 per element, published by the row owner.
__device__ __align__(16) unsigned int g_td[D];
// Sharded arrival counters, 128B stride -> 8 distinct L2 lines.
__device__ unsigned int g_bar[NBAR * 32];

// ---------------------------------------------------------------------------
// prep: interleave A,B into fp16 pairs; reset the barrier shards.
// ---------------------------------------------------------------------------
__global__ void __launch_bounds__(256) prep_kernel(const float* __restrict__ A,
                                                   const float* __restrict__ B) {
    if (blockIdx.x == 0 && threadIdx.x < NBAR * 32) g_bar[threadIdx.x] = 0;
    size_t i = (size_t)blockIdx.x * blockDim.x + threadIdx.x;  // float4 index
    float4 a = ((const float4*)A)[i];
    float4 b = ((const float4*)B)[i];
    uint4 o;
    __half2 p;
    p = __floats2half2_rn(a.x, b.x); o.x = *(unsigned int*)&p;   // lo=A, hi=B
    p = __floats2half2_rn(a.y, b.y); o.y = *(unsigned int*)&p;
    p = __floats2half2_rn(a.z, b.z); o.z = *(unsigned int*)&p;
    p = __floats2half2_rn(a.w, b.w); o.w = *(unsigned int*)&p;
    ((uint4*)g_AB)[i] = o;
}

// acc += Sum_j(A_j*t_j) + Sum_j(B_j*d_j) over 4 elements (pure HFMA2 + fold).
__device__ __forceinline__ float dotAB(uint4 m, uint4 v, float acc) {
    __half2 p = __hmul2(*(__half2*)&m.x, *(__half2*)&v.x);
    p = __hfma2(*(__half2*)&m.y, *(__half2*)&v.y, p);
    p = __hfma2(*(__half2*)&m.z, *(__half2*)&v.z, p);
    p = __hfma2(*(__half2*)&m.w, *(__half2*)&v.w, p);
    float2 f = __half22float2(p);
    return acc + f.x + f.y;
}

// ---------------------------------------------------------------------------
// Persistent recurrence kernel: 147 CTAs x 1024 threads, 28 rows/CTA.
// Same compute structure as the 308us kernel.  NEW: row owners publish a
// packed (theta, delta) half2 to g_td alongside the fp32 out row (delta from
// a register copy of last step's value — identical fp32 arithmetic), so
// staging is a single LDG.128 + STS.128 per thread (no s_t, no pack).
// Publish is merged into the warp-0 barrier sequence (3 syncs/step).
// SMEM: s_td 16K | part 512B | cached rows 192K = 208.5 KB.
// ---------------------------------------------------------------------------
__global__ void __launch_bounds__(NTHREADS, 1) rnn_kernel(const float* __restrict__ init,
                                                          float* __restrict__ out) {
    extern __shared__ char smem[];
    uint4*  s_td   = (uint4*)smem;                     // (t,d) half2    (16 KB)
    float*  s_part = (float*)(smem + 16384);           // partials       (512 B)
    uint4*  s_mat  = (uint4*)(smem + 16896);           // cached rows    (192 KB)

    const int tid  = threadIdx.x;
    const int warp = tid >> 5;
    const int lane = tid & 31;
    const int rg   = warp >> 2;                        // 0..7 (7 idle)
    const int ks   = warp & 3;                         // 0..3
    const int row_base = blockIdx.x * ROWS_PER_CTA;
    const int row0 = row_base + rg * 4;
    const bool rowOK  = (rg < 7) && (row0 < D);
    const bool cached = (rg < CACHED_ROWS / 4);        // rg 0..2 -> SMEM rows
    const int seg = ks * 256;                          // uint4 offset of segment

    // Preload cached rows into SMEM (once).  Clamp OOB rows of the last CTA.
#pragma unroll
    for (int it = 0; it < CACHED_ROWS; ++it) {
        int sr = min(row_base + it, D - 1);
        s_mat[it * 1024 + tid] = ((const uint4*)g_AB)[(size_t)sr * 1024 + tid];
    }

    // Streamed-row pointers (rg >= 3), clamped for the partially-OOB last CTA
    const uint4* r0 = (const uint4*)g_AB + (size_t)min(row0 + 0, D - 1) * 1024;
    const uint4* r1 = (const uint4*)g_AB + (size_t)min(row0 + 1, D - 1) * 1024;
    const uint4* r2 = (const uint4*)g_AB + (size_t)min(row0 + 2, D - 1) * 1024;
    const uint4* r3 = (const uint4*)g_AB + (size_t)min(row0 + 3, D - 1) * 1024;
    // Cached-row pointers (rg < 3)
    const uint4* c0 = s_mat + (size_t)(rg * 4 + 0) * 1024;
    const uint4* c1 = s_mat + (size_t)(rg * 4 + 1) * 1024;
    const uint4* c2 = s_mat + (size_t)(rg * 4 + 2) * 1024;
    const uint4* c3 = s_mat + (size_t)(rg * 4 + 3) * 1024;

    // Writer state: this thread owns row (row_base + tid) if tid < 28.
    // th_prev = theta_t[row] in fp32, carried across steps in a register.
    const int wrow = row_base + tid;
    const bool writer = (tid < ROWS_PER_CTA) && (wrow < D);
    float th_prev = writer ? init[D + wrow] : 0.f;     // theta_0[row]

    for (int t = 0; t < NSTEPS; ++t) {
        // ---- Stage (theta_t, delta_t) half2 pairs into s_td ----
        if (t == 0) {
            // From init: theta_0 = init[D..2D), theta_{-1} = init[0..D)
            float4 nt = ((const float4*)(init + D))[tid];
            float4 pt = ((const float4*)init)[tid];
            uint4 v;
            __half2 h;
            h = __floats2half2_rn(nt.x, nt.x - pt.x); v.x = *(unsigned int*)&h;
            h = __floats2half2_rn(nt.y, nt.y - pt.y); v.y = *(unsigned int*)&h;
            h = __floats2half2_rn(nt.z, nt.z - pt.z); v.z = *(unsigned int*)&h;
            h = __floats2half2_rn(nt.w, nt.w - pt.w); v.w = *(unsigned int*)&h;
            s_td[tid] = v;
        } else {
            s_td[tid] = __ldcg((const uint4*)g_td + tid);   // pre-packed by owners
        }
        __syncthreads();

        if (rowOK) {
            float a0 = 0.f, a1 = 0.f, a2 = 0.f, a3 = 0.f;
            if (cached) {
#pragma unroll 2
                for (int i = 0; i < 8; ++i) {
                    int idx = seg + i * 32 + lane;
                    uint4 v = s_td[idx];
                    a0 = dotAB(c0[idx], v, a0);
                    a1 = dotAB(c1[idx], v, a1);
                    a2 = dotAB(c2[idx], v, a2);
                    a3 = dotAB(c3[idx], v, a3);
                }
            } else {
#pragma unroll 2
                for (int i = 0; i < 8; ++i) {
                    int idx = seg + i * 32 + lane;
                    uint4 m0 = r0[idx];
                    uint4 m1 = r1[idx];
                    uint4 m2 = r2[idx];
                    uint4 m3 = r3[idx];
                    uint4 v = s_td[idx];
                    a0 = dotAB(m0, v, a0);
                    a1 = dotAB(m1, v, a1);
                    a2 = dotAB(m2, v, a2);
                    a3 = dotAB(m3, v, a3);
                }
            }
#pragma unroll
            for (int off = 16; off; off >>= 1) {
                a0 += __shfl_xor_sync(0xffffffffu, a0, off);
                a1 += __shfl_xor_sync(0xffffffffu, a1, off);
                a2 += __shfl_xor_sync(0xffffffffu, a2, off);
                a3 += __shfl_xor_sync(0xffffffffu, a3, off);
            }
            if (lane == 0) {
                s_part[(rg * 4 + 0) * 4 + ks] = a0;
                s_part[(rg * 4 + 1) * 4 + ks] = a1;
                s_part[(rg * 4 + 2) * 4 + ks] = a2;
                s_part[(rg * 4 + 3) * 4 + ks] = a3;
            }
        }
        __syncthreads();                               // partials ready

        // ---- Warp 0: combine, publish fp32 + packed fp16, run barrier ----
        if (warp == 0) {
            if (writer) {
                float v = (s_part[tid * 4 + 0] + s_part[tid * 4 + 1]) +
                          (s_part[tid * 4 + 2] + s_part[tid * 4 + 3]);
                __stcg(out + (size_t)t * D + wrow, v);
                float dlt = v - th_prev;               // exact fp32, from register
                th_prev = v;
                __half2 h = __floats2half2_rn(v, dlt);
                __stcg(&g_td[wrow], *(unsigned int*)&h);
            }
            __syncwarp();
            if (lane == 0) {
                __threadfence();                       // release rows + g_td
                atomicAdd(&g_bar[(blockIdx.x & (NBAR - 1)) * 32], 1u);
                const unsigned int target = (unsigned int)(t + 1) * NCTA;
                unsigned int sum;
                do {
                    sum = 0;
#pragma unroll
                    for (int k = 0; k < NBAR; ++k)
                        sum += *(volatile unsigned int*)&g_bar[k * 32];
                } while (sum < target);
                __threadfence();                       // acquire
            }
            __syncwarp();
        }
        __syncthreads();                               // release all warps
    }
}

// ---------------------------------------------------------------------------
// Launch: prep (convert + barrier reset), then ONE persistent kernel with
// opt-in 208.5 KB dynamic SMEM (1 CTA/SM, 147 co-resident).
// ---------------------------------------------------------------------------
extern "C" void kernel_launch(void* const* d_in, const int* in_sizes, int n_in,
                              void* d_out, int out_size) {
    const float* init = (const float*)d_in[0];  // [2, D]
    const float* A    = (const float*)d_in[1];  // [D, D]
    const float* B    = (const float*)d_in[2];  // [D, D]
    float* out = (float*)d_out;                 // [NSTEPS, D]

    const int smem_bytes = 16896 + CACHED_ROWS * 1024 * 16;  // 213,504 B
    cudaFuncSetAttribute(rnn_kernel, cudaFuncAttributeMaxDynamicSharedMemorySize,
                         smem_bytes);

    prep_kernel<<<(D * (size_t)D / 4) / 256, 256>>>(A, B);
    rnn_kernel<<<NCTA, NTHREADS, smem_bytes>>>(init, out);
}